// round 14
// baseline (speedup 1.0000x reference)
#include <cuda_runtime.h>
#include <cuda_fp16.h>
#include <cstdint>

#define BB 8
#define NN_ 8192
#define MM 2048
#define C1 128
#define C2 256
#define CIN 384
#define CO 256
#define NBX 512            // n-tiles total (BB * NN_/128)

typedef unsigned long long ull;

// ---------------- device scratch (no allocations allowed) ----------------
__device__ int    g_idx[BB * NN_];
__device__ __half g_x0h[(size_t)BB * CIN * NN_];     // X0^T fp16 [b][k][n] (48MB)
__device__ __half g_y0h[(size_t)BB * CO * NN_];      // y0 fp16 [b][o][n]  (32MB)
__device__ __half g_x1h[(size_t)BB * CO * NN_];      // X1 fp16 (post BN0+relu)
__device__ float  g_ab0[2 * CO];
__device__ float  g_ab1[2 * CO];
__device__ __half g_w0h[CO * CIN];
__device__ __half g_w1h[CO * CO];
__device__ float  g_psum[CO * NBX];
__device__ float  g_psq[CO * NBX];

// ---------------- helpers -------------------------------------------------
__device__ __forceinline__ ull f2_add(ull a, ull b) {
    ull r; asm("add.rn.f32x2 %0, %1, %2;" : "=l"(r) : "l"(a), "l"(b)); return r;
}
__device__ __forceinline__ ull f2_mul(ull a, ull b) {
    ull r; asm("mul.rn.f32x2 %0, %1, %2;" : "=l"(r) : "l"(a), "l"(b)); return r;
}
__device__ __forceinline__ ull f2_pack(float lo, float hi) {
    ull r; asm("mov.b64 %0, {%1, %2};" : "=l"(r) : "f"(lo), "f"(hi)); return r;
}
__device__ __forceinline__ void f2_unpack(float& lo, float& hi, ull v) {
    asm("mov.b64 {%0, %1}, %2;" : "=f"(lo), "=f"(hi) : "l"(v));
}
__device__ __forceinline__ uint32_t smem_u32(const void* p) {
    uint32_t a;
    asm("{ .reg .u64 t; cvta.to.shared.u64 t, %1; cvt.u32.u64 %0, t; }" : "=r"(a) : "l"(p));
    return a;
}
__device__ __forceinline__ void ldsm4(uint32_t& r0, uint32_t& r1, uint32_t& r2, uint32_t& r3,
                                      uint32_t addr) {
    asm volatile("ldmatrix.sync.aligned.m8n8.x4.shared.b16 {%0,%1,%2,%3}, [%4];"
                 : "=r"(r0), "=r"(r1), "=r"(r2), "=r"(r3) : "r"(addr));
}
__device__ __forceinline__ void ldsm4t(uint32_t& r0, uint32_t& r1, uint32_t& r2, uint32_t& r3,
                                       uint32_t addr) {
    asm volatile("ldmatrix.sync.aligned.m8n8.x4.trans.shared.b16 {%0,%1,%2,%3}, [%4];"
                 : "=r"(r0), "=r"(r1), "=r"(r2), "=r"(r3) : "r"(addr));
}
__device__ __forceinline__ void mma16816(float* c, const uint32_t* a, const uint32_t* b) {
    asm volatile("mma.sync.aligned.m16n8k16.row.col.f32.f16.f16.f32 "
                 "{%0,%1,%2,%3}, {%4,%5,%6,%7}, {%8,%9}, {%0,%1,%2,%3};"
                 : "+f"(c[0]), "+f"(c[1]), "+f"(c[2]), "+f"(c[3])
                 : "r"(a[0]), "r"(a[1]), "r"(a[2]), "r"(a[3]), "r"(b[0]), "r"(b[1]));
}
__device__ __forceinline__ uint32_t h2u(float a, float b) {
    __half2 h = __halves2half2(__float2half_rn(a), __float2half_rn(b));
    return *(uint32_t*)&h;
}
#define CP_ASYNC16(saddr, gptr) \
    asm volatile("cp.async.cg.shared.global [%0], [%1], 16;" :: "r"(saddr), "l"(gptr))
#define CP_COMMIT() asm volatile("cp.async.commit_group;" ::: "memory")
#define CP_WAIT0()  asm volatile("cp.async.wait_group 0;" ::: "memory")
#define CP_WAIT1()  asm volatile("cp.async.wait_group 1;" ::: "memory")

// ---------------- 1) nearest neighbor (bitwise-matching argmin) ----------
__global__ __launch_bounds__(256) void nn_kernel(const float* __restrict__ xyz1,
                                                 const float* __restrict__ xyz2) {
    __shared__ __align__(16) float nq[3][MM];
    const int b  = blockIdx.y;
    const int n0 = blockIdx.x * 512;
    const int tid = threadIdx.x;

    const float* x2 = xyz2 + (size_t)b * MM * 3;
    for (int m = tid; m < MM; m += 256) {
        nq[0][m] = -x2[3 * m + 0];
        nq[1][m] = -x2[3 * m + 1];
        nq[2][m] = -x2[3 * m + 2];
    }
    __syncthreads();

    const ull* qx2 = (const ull*)nq[0];
    const ull* qy2 = (const ull*)nq[1];
    const ull* qz2 = (const ull*)nq[2];

    const int ng0 = n0 + tid;
    const int ng1 = n0 + tid + 256;
    const float* p0 = xyz1 + ((size_t)b * NN_ + ng0) * 3;
    const float* p1 = xyz1 + ((size_t)b * NN_ + ng1) * 3;

    const ull px0 = f2_pack(p0[0], p0[0]), py0 = f2_pack(p0[1], p0[1]), pz0 = f2_pack(p0[2], p0[2]);
    const ull px1 = f2_pack(p1[0], p1[0]), py1 = f2_pack(p1[1], p1[1]), pz1 = f2_pack(p1[2], p1[2]);

    float be0 = 3.0e38f, bo0 = 3.0e38f, be1 = 3.0e38f, bo1 = 3.0e38f;
    int   ie0 = 0, io0 = 1, ie1 = 0, io1 = 1;

#pragma unroll 8
    for (int m2 = 0; m2 < MM / 2; ++m2) {
        const ull qx = qx2[m2], qy = qy2[m2], qz = qz2[m2];
        {
            ull dx = f2_add(px0, qx), dy = f2_add(py0, qy), dz = f2_add(pz0, qz);
            ull d  = f2_add(f2_add(f2_mul(dx, dx), f2_mul(dy, dy)), f2_mul(dz, dz));
            float dl, dh; f2_unpack(dl, dh, d);
            const bool pe = dl < be0, po = dh < bo0;
            be0 = pe ? dl : be0; ie0 = pe ? 2 * m2 : ie0;
            bo0 = po ? dh : bo0; io0 = po ? 2 * m2 + 1 : io0;
        }
        {
            ull dx = f2_add(px1, qx), dy = f2_add(py1, qy), dz = f2_add(pz1, qz);
            ull d  = f2_add(f2_add(f2_mul(dx, dx), f2_mul(dy, dy)), f2_mul(dz, dz));
            float dl, dh; f2_unpack(dl, dh, d);
            const bool pe = dl < be1, po = dh < bo1;
            be1 = pe ? dl : be1; ie1 = pe ? 2 * m2 : ie1;
            bo1 = po ? dh : bo1; io1 = po ? 2 * m2 + 1 : io1;
        }
    }
    int bi0 = ie0;
    if (bo0 < be0 || (bo0 == be0 && io0 < ie0)) bi0 = io0;
    int bi1 = ie1;
    if (bo1 < be1 || (bo1 == be1 && io1 < ie1)) bi1 = io1;

    g_idx[b * NN_ + ng0] = bi0;
    g_idx[b * NN_ + ng1] = bi1;
}

// ---------------- 2) weight convert (single fp16) --------------------------
__global__ __launch_bounds__(256) void prep_w(const float* __restrict__ w0,
                                              const float* __restrict__ w1) {
    const int i = blockIdx.x * 256 + threadIdx.x;
    if (i < CO * CIN) g_w0h[i] = __float2half_rn(w0[i]);
    if (i < CO * CO)  g_w1h[i] = __float2half_rn(w1[i]);
}

// ---------------- 3) build X0^T fp16 [b][k][n] (f1 convert + f2 gather) ---
// 256 threads, each owns 2 consecutive n; k-loop streams rows. f2 gather
// reads random offsets within an L1-resident 8KB row (reused 512x/block).
__global__ __launch_bounds__(256) void prep_x0h(const float* __restrict__ f1,
                                                const float* __restrict__ f2) {
    __shared__ int sidx[512];
    const int b = blockIdx.y, n0 = blockIdx.x * 512;
    const int tid = threadIdx.x;
    for (int i = tid; i < 512; i += 256) sidx[i] = g_idx[b * NN_ + n0 + i];
    __syncthreads();

    const int n = n0 + tid * 2;
    __half* dst = g_x0h + (size_t)b * CIN * NN_ + n;
    const float* f1b = f1 + ((size_t)b * C1) * NN_ + n;
#pragma unroll 4
    for (int k = 0; k < C1; ++k) {
        const float2 v = *(const float2*)(f1b + (size_t)k * NN_);
        *(uint32_t*)(dst + (size_t)k * NN_) = h2u(v.x, v.y);
    }
    const int i0 = sidx[tid * 2], i1 = sidx[tid * 2 + 1];
    const float* f2b = f2 + (size_t)b * C2 * MM;
#pragma unroll 4
    for (int c = 0; c < C2; ++c) {
        const float* row = f2b + (size_t)c * MM;
        *(uint32_t*)(dst + (size_t)(C1 + c) * NN_) = h2u(__ldg(row + i0), __ldg(row + i1));
    }
}

// ---------------- 4) build X1 fp16 = relu(a*y0h + b) ----------------------
__global__ __launch_bounds__(256) void prep_x1h() {
    const size_t i = ((size_t)blockIdx.x * 256 + threadIdx.x) * 8;
    const int k = (int)((i >> 13) & (CO - 1));
    const float a = g_ab0[k], b2 = g_ab0[CO + k];
    uint4 u = *(const uint4*)(g_y0h + i);
    uint32_t* pu = (uint32_t*)&u;
    uint32_t r[4];
#pragma unroll
    for (int q = 0; q < 4; ++q) {
        const __half2 h = *(__half2*)&pu[q];
        const float2 f = __half22float2(h);
        r[q] = h2u(fmaxf(fmaf(a, f.x, b2), 0.f), fmaxf(fmaf(a, f.y, b2), 0.f));
    }
    *(uint4*)(g_x1h + i) = make_uint4(r[0], r[1], r[2], r[3]);
}

// ---------------- 5) pure cp.async HMMA GEMM, CTA 256(o) x 128(n) ---------
// 256 threads, 8 warps 4(o)x2(n), warp tile 64x64. Both operands fp16 in
// global, k-major; feed = cp.async only (3-stage, 3 smem buffers). No LDG/
// convert/STS on the warp path -> regs drop, issue slots go to LDSM+HMMA.
#define PADK 72
#define PADN 136
#define W_TILE_B  (256 * PADK * 2)          // 36864
#define XT_TILE_B (64 * PADN * 2)           // 17408
#define BUF_B     (W_TILE_B + XT_TILE_B)    // 54272
#define GEMM_SMEM (3 * BUF_B + 512)         // 163328

template <int LAYER>
__global__ __launch_bounds__(256, 1) void gemm_mma(float* __restrict__ Yarg) {
    constexpr int KDIM = (LAYER == 0) ? CIN : CO;
    constexpr int NKB  = KDIM / 64;
    const __half* __restrict__ Wh = (LAYER == 0) ? g_w0h : g_w1h;
    const __half* __restrict__ Xt = (LAYER == 0) ? g_x0h : g_x1h;

    extern __shared__ __align__(16) char smem[];

    const int tid = threadIdx.x, wid = tid >> 5, lane = tid & 31;
    const int bx = blockIdx.x;
    const int b  = bx >> 6;
    const int n0 = (bx & 63) << 7;

    const int warp_o = (wid & 3) * 64;
    const int warp_n = (wid >> 2) * 64;

    const uint32_t sb = smem_u32(smem);
    const int arow = warp_o + (lane & 15);
    const int acol = (lane >> 4) * 8;
    const uint32_t aW_off = (uint32_t)(arow * PADK + acol) * 2;
    const int krow = (lane & 7) + ((lane >> 3) & 1) * 8;
    const int noff = warp_n + ((lane >> 4) & 1) * 8;
    const uint32_t aXt_off = (uint32_t)(krow * PADN + noff) * 2;

    float acc[4][8][4] = {};

    auto cp_wx = [&](int buf, int k0) {
        const uint32_t base = sb + buf * BUF_B;
        // W: 256 rows x 8 segs (16B) = 2048 chunks, 8/thread
#pragma unroll
        for (int it = 0; it < 8; ++it) {
            const int i = tid + it * 256;
            const int row = i >> 3, seg = i & 7;
            CP_ASYNC16(base + (uint32_t)(row * PADK + seg * 8) * 2,
                       Wh + (size_t)row * KDIM + k0 + seg * 8);
        }
        // X: 64 rows x 16 segs (16B) = 1024 chunks, 4/thread
        const uint32_t xbase = base + W_TILE_B;
#pragma unroll
        for (int it = 0; it < 4; ++it) {
            const int i = tid + it * 256;
            const int row = i >> 4, seg = i & 15;
            CP_ASYNC16(xbase + (uint32_t)(row * PADN + seg * 8) * 2,
                       Xt + ((size_t)(b * KDIM) + k0 + row) * NN_ + n0 + seg * 8);
        }
    };
    auto mma_kk = [&](int buf, int kk) {
        const uint32_t aW  = sb + buf * BUF_B + aW_off;
        const uint32_t aXt = sb + buf * BUF_B + W_TILE_B + aXt_off;
        uint32_t bh[4][4];
#pragma unroll
        for (int u = 0; u < 4; ++u)
            ldsm4t(bh[u][0], bh[u][1], bh[u][2], bh[u][3],
                   aXt + kk * 16 * PADN * 2 + u * 32);
#pragma unroll
        for (int t = 0; t < 4; ++t) {
            uint32_t a[4];
            ldsm4(a[0], a[1], a[2], a[3], aW + t * 16 * PADK * 2 + kk * 32);
#pragma unroll
            for (int j = 0; j < 8; ++j) {
                const uint32_t* pb = &bh[j >> 1][(j & 1) * 2];
                mma16816(acc[t][j], a, pb);
            }
        }
    };

    // ---- prologue: stage blocks 0 and 1 ----
    cp_wx(0, 0); CP_COMMIT();
    if (NKB > 1) { cp_wx(1, 64); CP_COMMIT(); CP_WAIT1(); }
    else CP_WAIT0();
    __syncthreads();

    // ---- main pipeline (3 buffers, 2-deep prefetch) ----
    for (int kb = 0; kb < NKB; ++kb) {
        const int cur = kb % 3;
        mma_kk(cur, 0);
        if (kb + 2 < NKB) { cp_wx((kb + 2) % 3, (kb + 2) * 64); CP_COMMIT(); }
        mma_kk(cur, 1);
        mma_kk(cur, 2);
        mma_kk(cur, 3);
        if (kb + 1 < NKB) {
            if (kb + 2 < NKB) CP_WAIT1(); else CP_WAIT0();
            __syncthreads();
        }
    }

    // ---- Y store ----
    const int ncol = n0 + warp_n + (lane & 3) * 2;
    if (LAYER == 0) {
#pragma unroll
        for (int t = 0; t < 4; ++t) {
            const int orow = warp_o + t * 16 + (lane >> 2);
            __half* d0 = g_y0h + ((size_t)(b * CO) + orow) * NN_ + ncol;
            __half* d1 = d0 + 8 * NN_;
#pragma unroll
            for (int j = 0; j < 8; ++j) {
                *(uint32_t*)(d0 + j * 8) = h2u(acc[t][j][0], acc[t][j][1]);
                *(uint32_t*)(d1 + j * 8) = h2u(acc[t][j][2], acc[t][j][3]);
            }
        }
    } else {
#pragma unroll
        for (int t = 0; t < 4; ++t) {
            const int orow = warp_o + t * 16 + (lane >> 2);
            float* d0 = Yarg + ((size_t)(b * CO) + orow) * NN_ + ncol;
            float* d1 = d0 + 8 * NN_;
#pragma unroll
            for (int j = 0; j < 8; ++j) {
                *(float2*)(d0 + j * 8) = make_float2(acc[t][j][0], acc[t][j][1]);
                *(float2*)(d1 + j * 8) = make_float2(acc[t][j][2], acc[t][j][3]);
            }
        }
    }

    // ---- deterministic stats partials (from fp32 accumulators) ----
    float rs[8] = {}, rq[8] = {};
#pragma unroll
    for (int t = 0; t < 4; ++t)
#pragma unroll
        for (int j = 0; j < 8; ++j) {
            rs[t * 2 + 0] += acc[t][j][0] + acc[t][j][1];
            rq[t * 2 + 0] += acc[t][j][0] * acc[t][j][0] + acc[t][j][1] * acc[t][j][1];
            rs[t * 2 + 1] += acc[t][j][2] + acc[t][j][3];
            rq[t * 2 + 1] += acc[t][j][2] * acc[t][j][2] + acc[t][j][3] * acc[t][j][3];
        }
#pragma unroll
    for (int w = 0; w < 8; ++w) {
        rs[w] += __shfl_xor_sync(0xffffffffu, rs[w], 1);
        rs[w] += __shfl_xor_sync(0xffffffffu, rs[w], 2);
        rq[w] += __shfl_xor_sync(0xffffffffu, rq[w], 1);
        rq[w] += __shfl_xor_sync(0xffffffffu, rq[w], 2);
    }
    __syncthreads();
    float* sSum = (float*)smem;        // [2 n-groups][256 rows]
    float* sSq  = sSum + 512;
    if ((lane & 3) == 0) {
        const int h = (wid >> 2) * 256;
#pragma unroll
        for (int t = 0; t < 4; ++t) {
            const int g = warp_o + t * 16 + (lane >> 2);
            sSum[h + g]     = rs[t * 2 + 0];
            sSum[h + g + 8] = rs[t * 2 + 1];
            sSq[h + g]      = rq[t * 2 + 0];
            sSq[h + g + 8]  = rq[t * 2 + 1];
        }
    }
    __syncthreads();
    if (tid < 256) {
        g_psum[(size_t)tid * NBX + bx] = sSum[tid] + sSum[256 + tid];
        g_psq[(size_t)tid * NBX + bx]  = sSq[tid] + sSq[256 + tid];
    }
}

// ---------------- 6) stats reduce: partials -> BN affine ------------------
template <int LAYER>
__global__ __launch_bounds__(256) void stats_reduce(const float* __restrict__ gamma,
                                                    const float* __restrict__ beta) {
    const int o = blockIdx.x, tid = threadIdx.x;
    float s = g_psum[(size_t)o * NBX + tid] + g_psum[(size_t)o * NBX + 256 + tid];
    float q = g_psq[(size_t)o * NBX + tid] + g_psq[(size_t)o * NBX + 256 + tid];
    __shared__ float ss[256], sq[256];
    ss[tid] = s; sq[tid] = q;
    __syncthreads();
    for (int st = 128; st > 0; st >>= 1) {
        if (tid < st) { ss[tid] += ss[tid + st]; sq[tid] += sq[tid + st]; }
        __syncthreads();
    }
    if (tid == 0) {
        const float inv = 1.f / (float)(BB * NN_);
        const float mu  = ss[0] * inv;
        const float var = sq[0] * inv - mu * mu;
        const float a   = gamma[o] * rsqrtf(var + 1e-5f);
        float* ab = (LAYER == 0) ? g_ab0 : g_ab1;
        ab[o]      = a;
        ab[CO + o] = beta[o] - mu * a;
    }
}

// ---------------- 7) final BN1 + ReLU in place on d_out ------------------
__global__ __launch_bounds__(256) void bnrelu_kernel(float* __restrict__ y) {
    const size_t i = ((size_t)blockIdx.x * blockDim.x + threadIdx.x) * 4;
    const int c = (int)((i >> 13) & (CO - 1));
    const float a = g_ab1[c], bb = g_ab1[CO + c];
    float4 v = *(float4*)(y + i);
    v.x = fmaxf(fmaf(a, v.x, bb), 0.f);
    v.y = fmaxf(fmaf(a, v.y, bb), 0.f);
    v.z = fmaxf(fmaf(a, v.z, bb), 0.f);
    v.w = fmaxf(fmaf(a, v.w, bb), 0.f);
    *(float4*)(y + i) = v;
}

// ---------------- launcher ------------------------------------------------
extern "C" void kernel_launch(void* const* d_in, const int* in_sizes, int n_in,
                              void* d_out, int out_size) {
    const float* xyz1   = (const float*)d_in[0];
    const float* xyz2   = (const float*)d_in[1];
    const float* f1     = (const float*)d_in[2];
    const float* f2     = (const float*)d_in[3];
    const float* w0     = (const float*)d_in[4];
    const float* gamma0 = (const float*)d_in[5];
    const float* beta0  = (const float*)d_in[6];
    const float* w1     = (const float*)d_in[7];
    const float* gamma1 = (const float*)d_in[8];
    const float* beta1  = (const float*)d_in[9];
    float* out = (float*)d_out;

    cudaFuncSetAttribute(gemm_mma<0>, cudaFuncAttributeMaxDynamicSharedMemorySize, GEMM_SMEM);
    cudaFuncSetAttribute(gemm_mma<1>, cudaFuncAttributeMaxDynamicSharedMemorySize, GEMM_SMEM);

    nn_kernel<<<dim3(NN_ / 512, BB), 256>>>(xyz1, xyz2);
    prep_w<<<(CO * CIN + 255) / 256, 256>>>(w0, w1);
    prep_x0h<<<dim3(NN_ / 512, BB), 256>>>(f1, f2);

    gemm_mma<0><<<NBX, 256, GEMM_SMEM>>>(nullptr);
    stats_reduce<0><<<CO, 256>>>(gamma0, beta0);
    prep_x1h<<<(int)(((size_t)BB * CO * NN_) / (8 * 256)), 256>>>();

    gemm_mma<1><<<NBX, 256, GEMM_SMEM>>>(out);
    stats_reduce<1><<<CO, 256>>>(gamma1, beta1);

    bnrelu_kernel<<<(BB * CO * NN_) / (4 * 256), 256>>>(out);
}

// round 15
// speedup vs baseline: 1.1323x; 1.1323x over previous
#include <cuda_runtime.h>
#include <cuda_fp16.h>
#include <cstdint>

#define BB 8
#define NN_ 8192
#define MM 2048
#define C1 128
#define C2 256
#define CIN 384
#define CO 256
#define NBX 512            // n-tiles total (BB * NN_/128)

typedef unsigned long long ull;

// ---------------- device scratch (no allocations allowed) ----------------
__device__ int    g_idx[BB * NN_];
__device__ float  g_f2t[(size_t)BB * MM * C2];       // f2 transposed [b][m][c]
__device__ __half g_x0h[(size_t)BB * CIN * NN_];     // X0^T fp16 [b][k][n]
__device__ __half g_y0h[(size_t)BB * CO * NN_];      // y0 fp16 [b][o][n]
__device__ __half g_x1h[(size_t)BB * CO * NN_];      // X1 fp16 (post BN0+relu)
__device__ float  g_ab0[2 * CO];
__device__ float  g_ab1[2 * CO];
__device__ __half g_w0h[CO * CIN];
__device__ __half g_w1h[CO * CO];
__device__ float  g_psum[CO * NBX];
__device__ float  g_psq[CO * NBX];

// ---------------- helpers -------------------------------------------------
__device__ __forceinline__ ull f2_add(ull a, ull b) {
    ull r; asm("add.rn.f32x2 %0, %1, %2;" : "=l"(r) : "l"(a), "l"(b)); return r;
}
__device__ __forceinline__ ull f2_mul(ull a, ull b) {
    ull r; asm("mul.rn.f32x2 %0, %1, %2;" : "=l"(r) : "l"(a), "l"(b)); return r;
}
__device__ __forceinline__ ull f2_pack(float lo, float hi) {
    ull r; asm("mov.b64 %0, {%1, %2};" : "=l"(r) : "f"(lo), "f"(hi)); return r;
}
__device__ __forceinline__ void f2_unpack(float& lo, float& hi, ull v) {
    asm("mov.b64 {%0, %1}, %2;" : "=f"(lo), "=f"(hi) : "l"(v));
}
__device__ __forceinline__ uint32_t smem_u32(const void* p) {
    uint32_t a;
    asm("{ .reg .u64 t; cvta.to.shared.u64 t, %1; cvt.u32.u64 %0, t; }" : "=r"(a) : "l"(p));
    return a;
}
__device__ __forceinline__ void ldsm4(uint32_t& r0, uint32_t& r1, uint32_t& r2, uint32_t& r3,
                                      uint32_t addr) {
    asm volatile("ldmatrix.sync.aligned.m8n8.x4.shared.b16 {%0,%1,%2,%3}, [%4];"
                 : "=r"(r0), "=r"(r1), "=r"(r2), "=r"(r3) : "r"(addr));
}
__device__ __forceinline__ void ldsm4t(uint32_t& r0, uint32_t& r1, uint32_t& r2, uint32_t& r3,
                                       uint32_t addr) {
    asm volatile("ldmatrix.sync.aligned.m8n8.x4.trans.shared.b16 {%0,%1,%2,%3}, [%4];"
                 : "=r"(r0), "=r"(r1), "=r"(r2), "=r"(r3) : "r"(addr));
}
__device__ __forceinline__ void mma16816(float* c, const uint32_t* a, const uint32_t* b) {
    asm volatile("mma.sync.aligned.m16n8k16.row.col.f32.f16.f16.f32 "
                 "{%0,%1,%2,%3}, {%4,%5,%6,%7}, {%8,%9}, {%0,%1,%2,%3};"
                 : "+f"(c[0]), "+f"(c[1]), "+f"(c[2]), "+f"(c[3])
                 : "r"(a[0]), "r"(a[1]), "r"(a[2]), "r"(a[3]), "r"(b[0]), "r"(b[1]));
}
__device__ __forceinline__ uint32_t h2u(float a, float b) {
    __half2 h = __halves2half2(__float2half_rn(a), __float2half_rn(b));
    return *(uint32_t*)&h;
}
#define CP_ASYNC16(saddr, gptr) \
    asm volatile("cp.async.cg.shared.global [%0], [%1], 16;" :: "r"(saddr), "l"(gptr))
#define CP_COMMIT() asm volatile("cp.async.commit_group;" ::: "memory")
#define CP_WAIT0()  asm volatile("cp.async.wait_group 0;" ::: "memory")
#define CP_WAIT1()  asm volatile("cp.async.wait_group 1;" ::: "memory")

// ---------------- 1) nearest neighbor (bitwise-matching argmin) ----------
__global__ __launch_bounds__(256) void nn_kernel(const float* __restrict__ xyz1,
                                                 const float* __restrict__ xyz2) {
    __shared__ __align__(16) float nq[3][MM];
    const int b  = blockIdx.y;
    const int n0 = blockIdx.x * 512;
    const int tid = threadIdx.x;

    const float* x2 = xyz2 + (size_t)b * MM * 3;
    for (int m = tid; m < MM; m += 256) {
        nq[0][m] = -x2[3 * m + 0];
        nq[1][m] = -x2[3 * m + 1];
        nq[2][m] = -x2[3 * m + 2];
    }
    __syncthreads();

    const ull* qx2 = (const ull*)nq[0];
    const ull* qy2 = (const ull*)nq[1];
    const ull* qz2 = (const ull*)nq[2];

    const int ng0 = n0 + tid;
    const int ng1 = n0 + tid + 256;
    const float* p0 = xyz1 + ((size_t)b * NN_ + ng0) * 3;
    const float* p1 = xyz1 + ((size_t)b * NN_ + ng1) * 3;

    const ull px0 = f2_pack(p0[0], p0[0]), py0 = f2_pack(p0[1], p0[1]), pz0 = f2_pack(p0[2], p0[2]);
    const ull px1 = f2_pack(p1[0], p1[0]), py1 = f2_pack(p1[1], p1[1]), pz1 = f2_pack(p1[2], p1[2]);

    float be0 = 3.0e38f, bo0 = 3.0e38f, be1 = 3.0e38f, bo1 = 3.0e38f;
    int   ie0 = 0, io0 = 1, ie1 = 0, io1 = 1;

#pragma unroll 8
    for (int m2 = 0; m2 < MM / 2; ++m2) {
        const ull qx = qx2[m2], qy = qy2[m2], qz = qz2[m2];
        {
            ull dx = f2_add(px0, qx), dy = f2_add(py0, qy), dz = f2_add(pz0, qz);
            ull d  = f2_add(f2_add(f2_mul(dx, dx), f2_mul(dy, dy)), f2_mul(dz, dz));
            float dl, dh; f2_unpack(dl, dh, d);
            const bool pe = dl < be0, po = dh < bo0;
            be0 = pe ? dl : be0; ie0 = pe ? 2 * m2 : ie0;
            bo0 = po ? dh : bo0; io0 = po ? 2 * m2 + 1 : io0;
        }
        {
            ull dx = f2_add(px1, qx), dy = f2_add(py1, qy), dz = f2_add(pz1, qz);
            ull d  = f2_add(f2_add(f2_mul(dx, dx), f2_mul(dy, dy)), f2_mul(dz, dz));
            float dl, dh; f2_unpack(dl, dh, d);
            const bool pe = dl < be1, po = dh < bo1;
            be1 = pe ? dl : be1; ie1 = pe ? 2 * m2 : ie1;
            bo1 = po ? dh : bo1; io1 = po ? 2 * m2 + 1 : io1;
        }
    }
    int bi0 = ie0;
    if (bo0 < be0 || (bo0 == be0 && io0 < ie0)) bi0 = io0;
    int bi1 = ie1;
    if (bo1 < be1 || (bo1 == be1 && io1 < ie1)) bi1 = io1;

    g_idx[b * NN_ + ng0] = bi0;
    g_idx[b * NN_ + ng1] = bi1;
}

// ---------------- 2) weight convert (single fp16) --------------------------
__global__ __launch_bounds__(256) void prep_w(const float* __restrict__ w0,
                                              const float* __restrict__ w1) {
    const int i = blockIdx.x * 256 + threadIdx.x;
    if (i < CO * CIN) g_w0h[i] = __float2half_rn(w0[i]);
    if (i < CO * CO)  g_w1h[i] = __float2half_rn(w1[i]);
}

// ---------------- 3) transpose f2 -> [b][m][c] -----------------------------
__global__ void prep_f2t(const float* __restrict__ f2) {
    __shared__ float t[32][33];
    const int b = blockIdx.z, m0 = blockIdx.x * 32, c0 = blockIdx.y * 32;
    const int tx = threadIdx.x, ty = threadIdx.y;  // 32x8
#pragma unroll
    for (int k = 0; k < 4; k++)
        t[ty + 8 * k][tx] = f2[((size_t)(b * C2) + c0 + ty + 8 * k) * MM + m0 + tx];
    __syncthreads();
#pragma unroll
    for (int k = 0; k < 4; k++)
        g_f2t[((size_t)(b * MM) + m0 + ty + 8 * k) * C2 + c0 + tx] = t[tx][ty + 8 * k];
}

// ---------------- 4a) X0 f1 region: flat fp32->fp16 convert ---------------
// x0h[b][k][n] = fp16(f1[b][k][n]) for k<128. 8 elems/thread, 4096 blocks.
__global__ __launch_bounds__(256) void prep_x0f1(const float* __restrict__ f1) {
    const size_t i = ((size_t)blockIdx.x * 256 + threadIdx.x) * 8;   // within b
    const int b = blockIdx.y;
    const float4 a = *(const float4*)(f1 + (size_t)b * C1 * NN_ + i);
    const float4 c = *(const float4*)(f1 + (size_t)b * C1 * NN_ + i + 4);
    __half* dst = g_x0h + (size_t)b * CIN * NN_ + i;
    *(uint4*)dst = make_uint4(h2u(a.x, a.y), h2u(a.z, a.w), h2u(c.x, c.y), h2u(c.z, c.w));
}

// ---------------- 4b) X0 f2 region: gather from f2t rows -------------------
// 2 n per thread; reads two contiguous 1KB f2t rows; writes warp-coherent
// 128B (32 threads x uint32) per k. grid (NN_/512, BB), 256 thr.
__global__ __launch_bounds__(256) void prep_x0f2() {
    const int b = blockIdx.y, n0 = blockIdx.x * 512;
    const int tid = threadIdx.x;
    const int n = n0 + tid * 2;
    const int i0 = g_idx[b * NN_ + n];
    const int i1 = g_idx[b * NN_ + n + 1];
    const float4* rA = (const float4*)(g_f2t + ((size_t)(b * MM) + i0) * C2);
    const float4* rB = (const float4*)(g_f2t + ((size_t)(b * MM) + i1) * C2);
    __half* dst = g_x0h + ((size_t)(b * CIN) + C1) * NN_ + n;
#pragma unroll 4
    for (int kc = 0; kc < C2 / 4; ++kc) {
        const float4 va = rA[kc];
        const float4 vb = rB[kc];
        *(uint32_t*)(dst + (size_t)(kc * 4 + 0) * NN_) = h2u(va.x, vb.x);
        *(uint32_t*)(dst + (size_t)(kc * 4 + 1) * NN_) = h2u(va.y, vb.y);
        *(uint32_t*)(dst + (size_t)(kc * 4 + 2) * NN_) = h2u(va.z, vb.z);
        *(uint32_t*)(dst + (size_t)(kc * 4 + 3) * NN_) = h2u(va.w, vb.w);
    }
}

// ---------------- 5) build X1 fp16 = relu(a*y0h + b) ----------------------
__global__ __launch_bounds__(256) void prep_x1h() {
    const size_t i = ((size_t)blockIdx.x * 256 + threadIdx.x) * 8;
    const int k = (int)((i >> 13) & (CO - 1));
    const float a = g_ab0[k], b2 = g_ab0[CO + k];
    uint4 u = *(const uint4*)(g_y0h + i);
    uint32_t* pu = (uint32_t*)&u;
    uint32_t r[4];
#pragma unroll
    for (int q = 0; q < 4; ++q) {
        const __half2 h = *(__half2*)&pu[q];
        const float2 f = __half22float2(h);
        r[q] = h2u(fmaxf(fmaf(a, f.x, b2), 0.f), fmaxf(fmaf(a, f.y, b2), 0.f));
    }
    *(uint4*)(g_x1h + i) = make_uint4(r[0], r[1], r[2], r[3]);
}

// ---------------- 6) pure cp.async HMMA GEMM, CTA 256(o) x 128(n) ---------
#define PADK 72
#define PADN 136
#define W_TILE_B  (256 * PADK * 2)          // 36864
#define XT_TILE_B (64 * PADN * 2)           // 17408
#define BUF_B     (W_TILE_B + XT_TILE_B)    // 54272
#define GEMM_SMEM (3 * BUF_B + 512)         // 163328

template <int LAYER>
__global__ __launch_bounds__(256, 1) void gemm_mma(float* __restrict__ Yarg) {
    constexpr int KDIM = (LAYER == 0) ? CIN : CO;
    constexpr int NKB  = KDIM / 64;
    const __half* __restrict__ Wh = (LAYER == 0) ? g_w0h : g_w1h;
    const __half* __restrict__ Xt = (LAYER == 0) ? g_x0h : g_x1h;

    extern __shared__ __align__(16) char smem[];

    const int tid = threadIdx.x, wid = tid >> 5, lane = tid & 31;
    const int bx = blockIdx.x;
    const int b  = bx >> 6;
    const int n0 = (bx & 63) << 7;

    const int warp_o = (wid & 3) * 64;
    const int warp_n = (wid >> 2) * 64;

    const uint32_t sb = smem_u32(smem);
    const int arow = warp_o + (lane & 15);
    const int acol = (lane >> 4) * 8;
    const uint32_t aW_off = (uint32_t)(arow * PADK + acol) * 2;
    const int krow = (lane & 7) + ((lane >> 3) & 1) * 8;
    const int noff = warp_n + ((lane >> 4) & 1) * 8;
    const uint32_t aXt_off = (uint32_t)(krow * PADN + noff) * 2;

    float acc[4][8][4] = {};

    auto cp_wx = [&](int buf, int k0) {
        const uint32_t base = sb + buf * BUF_B;
#pragma unroll
        for (int it = 0; it < 8; ++it) {
            const int i = tid + it * 256;
            const int row = i >> 3, seg = i & 7;
            CP_ASYNC16(base + (uint32_t)(row * PADK + seg * 8) * 2,
                       Wh + (size_t)row * KDIM + k0 + seg * 8);
        }
        const uint32_t xbase = base + W_TILE_B;
#pragma unroll
        for (int it = 0; it < 4; ++it) {
            const int i = tid + it * 256;
            const int row = i >> 4, seg = i & 15;
            CP_ASYNC16(xbase + (uint32_t)(row * PADN + seg * 8) * 2,
                       Xt + ((size_t)(b * KDIM) + k0 + row) * NN_ + n0 + seg * 8);
        }
    };
    auto mma_kk = [&](int buf, int kk) {
        const uint32_t aW  = sb + buf * BUF_B + aW_off;
        const uint32_t aXt = sb + buf * BUF_B + W_TILE_B + aXt_off;
        uint32_t bh[4][4];
#pragma unroll
        for (int u = 0; u < 4; ++u)
            ldsm4t(bh[u][0], bh[u][1], bh[u][2], bh[u][3],
                   aXt + kk * 16 * PADN * 2 + u * 32);
#pragma unroll
        for (int t = 0; t < 4; ++t) {
            uint32_t a[4];
            ldsm4(a[0], a[1], a[2], a[3], aW + t * 16 * PADK * 2 + kk * 32);
#pragma unroll
            for (int j = 0; j < 8; ++j) {
                const uint32_t* pb = &bh[j >> 1][(j & 1) * 2];
                mma16816(acc[t][j], a, pb);
            }
        }
    };

    cp_wx(0, 0); CP_COMMIT();
    if (NKB > 1) { cp_wx(1, 64); CP_COMMIT(); CP_WAIT1(); }
    else CP_WAIT0();
    __syncthreads();

    for (int kb = 0; kb < NKB; ++kb) {
        const int cur = kb % 3;
        mma_kk(cur, 0);
        if (kb + 2 < NKB) { cp_wx((kb + 2) % 3, (kb + 2) * 64); CP_COMMIT(); }
        mma_kk(cur, 1);
        mma_kk(cur, 2);
        mma_kk(cur, 3);
        if (kb + 1 < NKB) {
            if (kb + 2 < NKB) CP_WAIT1(); else CP_WAIT0();
            __syncthreads();
        }
    }

    // ---- Y store ----
    const int ncol = n0 + warp_n + (lane & 3) * 2;
    if (LAYER == 0) {
#pragma unroll
        for (int t = 0; t < 4; ++t) {
            const int orow = warp_o + t * 16 + (lane >> 2);
            __half* d0 = g_y0h + ((size_t)(b * CO) + orow) * NN_ + ncol;
            __half* d1 = d0 + 8 * NN_;
#pragma unroll
            for (int j = 0; j < 8; ++j) {
                *(uint32_t*)(d0 + j * 8) = h2u(acc[t][j][0], acc[t][j][1]);
                *(uint32_t*)(d1 + j * 8) = h2u(acc[t][j][2], acc[t][j][3]);
            }
        }
    } else {
#pragma unroll
        for (int t = 0; t < 4; ++t) {
            const int orow = warp_o + t * 16 + (lane >> 2);
            float* d0 = Yarg + ((size_t)(b * CO) + orow) * NN_ + ncol;
            float* d1 = d0 + 8 * NN_;
#pragma unroll
            for (int j = 0; j < 8; ++j) {
                *(float2*)(d0 + j * 8) = make_float2(acc[t][j][0], acc[t][j][1]);
                *(float2*)(d1 + j * 8) = make_float2(acc[t][j][2], acc[t][j][3]);
            }
        }
    }

    // ---- deterministic stats partials (from fp32 accumulators) ----
    float rs[8] = {}, rq[8] = {};
#pragma unroll
    for (int t = 0; t < 4; ++t)
#pragma unroll
        for (int j = 0; j < 8; ++j) {
            rs[t * 2 + 0] += acc[t][j][0] + acc[t][j][1];
            rq[t * 2 + 0] += acc[t][j][0] * acc[t][j][0] + acc[t][j][1] * acc[t][j][1];
            rs[t * 2 + 1] += acc[t][j][2] + acc[t][j][3];
            rq[t * 2 + 1] += acc[t][j][2] * acc[t][j][2] + acc[t][j][3] * acc[t][j][3];
        }
#pragma unroll
    for (int w = 0; w < 8; ++w) {
        rs[w] += __shfl_xor_sync(0xffffffffu, rs[w], 1);
        rs[w] += __shfl_xor_sync(0xffffffffu, rs[w], 2);
        rq[w] += __shfl_xor_sync(0xffffffffu, rq[w], 1);
        rq[w] += __shfl_xor_sync(0xffffffffu, rq[w], 2);
    }
    __syncthreads();
    float* sSum = (float*)smem;        // [2 n-groups][256 rows]
    float* sSq  = sSum + 512;
    if ((lane & 3) == 0) {
        const int h = (wid >> 2) * 256;
#pragma unroll
        for (int t = 0; t < 4; ++t) {
            const int g = warp_o + t * 16 + (lane >> 2);
            sSum[h + g]     = rs[t * 2 + 0];
            sSum[h + g + 8] = rs[t * 2 + 1];
            sSq[h + g]      = rq[t * 2 + 0];
            sSq[h + g + 8]  = rq[t * 2 + 1];
        }
    }
    __syncthreads();
    if (tid < 256) {
        g_psum[(size_t)tid * NBX + bx] = sSum[tid] + sSum[256 + tid];
        g_psq[(size_t)tid * NBX + bx]  = sSq[tid] + sSq[256 + tid];
    }
}

// ---------------- 7) stats reduce: partials -> BN affine ------------------
template <int LAYER>
__global__ __launch_bounds__(256) void stats_reduce(const float* __restrict__ gamma,
                                                    const float* __restrict__ beta) {
    const int o = blockIdx.x, tid = threadIdx.x;
    float s = g_psum[(size_t)o * NBX + tid] + g_psum[(size_t)o * NBX + 256 + tid];
    float q = g_psq[(size_t)o * NBX + tid] + g_psq[(size_t)o * NBX + 256 + tid];
    __shared__ float ss[256], sq[256];
    ss[tid] = s; sq[tid] = q;
    __syncthreads();
    for (int st = 128; st > 0; st >>= 1) {
        if (tid < st) { ss[tid] += ss[tid + st]; sq[tid] += sq[tid + st]; }
        __syncthreads();
    }
    if (tid == 0) {
        const float inv = 1.f / (float)(BB * NN_);
        const float mu  = ss[0] * inv;
        const float var = sq[0] * inv - mu * mu;
        const float a   = gamma[o] * rsqrtf(var + 1e-5f);
        float* ab = (LAYER == 0) ? g_ab0 : g_ab1;
        ab[o]      = a;
        ab[CO + o] = beta[o] - mu * a;
    }
}

// ---------------- 8) final BN1 + ReLU in place on d_out ------------------
__global__ __launch_bounds__(256) void bnrelu_kernel(float* __restrict__ y) {
    const size_t i = ((size_t)blockIdx.x * blockDim.x + threadIdx.x) * 4;
    const int c = (int)((i >> 13) & (CO - 1));
    const float a = g_ab1[c], bb = g_ab1[CO + c];
    float4 v = *(float4*)(y + i);
    v.x = fmaxf(fmaf(a, v.x, bb), 0.f);
    v.y = fmaxf(fmaf(a, v.y, bb), 0.f);
    v.z = fmaxf(fmaf(a, v.z, bb), 0.f);
    v.w = fmaxf(fmaf(a, v.w, bb), 0.f);
    *(float4*)(y + i) = v;
}

// ---------------- launcher ------------------------------------------------
extern "C" void kernel_launch(void* const* d_in, const int* in_sizes, int n_in,
                              void* d_out, int out_size) {
    const float* xyz1   = (const float*)d_in[0];
    const float* xyz2   = (const float*)d_in[1];
    const float* f1     = (const float*)d_in[2];
    const float* f2     = (const float*)d_in[3];
    const float* w0     = (const float*)d_in[4];
    const float* gamma0 = (const float*)d_in[5];
    const float* beta0  = (const float*)d_in[6];
    const float* w1     = (const float*)d_in[7];
    const float* gamma1 = (const float*)d_in[8];
    const float* beta1  = (const float*)d_in[9];
    float* out = (float*)d_out;

    cudaFuncSetAttribute(gemm_mma<0>, cudaFuncAttributeMaxDynamicSharedMemorySize, GEMM_SMEM);
    cudaFuncSetAttribute(gemm_mma<1>, cudaFuncAttributeMaxDynamicSharedMemorySize, GEMM_SMEM);

    nn_kernel<<<dim3(NN_ / 512, BB), 256>>>(xyz1, xyz2);
    prep_w<<<(CO * CIN + 255) / 256, 256>>>(w0, w1);
    prep_f2t<<<dim3(MM / 32, C2 / 32, BB), dim3(32, 8)>>>(f2);
    prep_x0f1<<<dim3((C1 * NN_) / (256 * 8), BB), 256>>>(f1);
    prep_x0f2<<<dim3(NN_ / 512, BB), 256>>>();

    gemm_mma<0><<<NBX, 256, GEMM_SMEM>>>(nullptr);
    stats_reduce<0><<<CO, 256>>>(gamma0, beta0);
    prep_x1h<<<(int)(((size_t)BB * CO * NN_) / (8 * 256)), 256>>>();

    gemm_mma<1><<<NBX, 256, GEMM_SMEM>>>(out);
    stats_reduce<1><<<CO, 256>>>(gamma1, beta1);

    bnrelu_kernel<<<(BB * CO * NN_) / (4 * 256), 256>>>(out);
}